// round 10
// baseline (speedup 1.0000x reference)
#include <cuda_runtime.h>
#include <cuda_bf16.h>
#include <math.h>
#include <stdint.h>

typedef unsigned long long u64;

#define TOKENS 1024
#define CDIM   512
#define QKVD   1536
#define NSEQ   256
#define HEADS  8
#define DH     64
#define QT     32
#define EPSF   1e-6f
#define T_SMALL 0.009f
#define CH     132                      // q-side chunk stride (floats)

// ---------------- packed f32x2 helpers ----------------
__device__ __forceinline__ u64 pk2(float lo, float hi) {
    u64 r; asm("mov.b64 %0,{%1,%2};" : "=l"(r) : "f"(lo), "f"(hi)); return r;
}
__device__ __forceinline__ void up2(u64 v, float& lo, float& hi) {
    asm("mov.b64 {%0,%1},%2;" : "=f"(lo), "=f"(hi) : "l"(v));
}
__device__ __forceinline__ u64 fadd2(u64 a, u64 b) {
    u64 r; asm("add.rn.f32x2 %0,%1,%2;" : "=l"(r) : "l"(a), "l"(b)); return r;
}
__device__ __forceinline__ u64 fmul2(u64 a, u64 b) {
    u64 r; asm("mul.rn.f32x2 %0,%1,%2;" : "=l"(r) : "l"(a), "l"(b)); return r;
}
__device__ __forceinline__ u64 ffma2(u64 a, u64 b, u64 c) {
    u64 r; asm("fma.rn.f32x2 %0,%1,%2,%3;" : "=l"(r) : "l"(a), "l"(b), "l"(c)); return r;
}
__device__ __forceinline__ uint32_t smem_u32(const void* p) {
    uint32_t a;
    asm("{ .reg .u64 t; cvta.to.shared.u64 t, %1; cvt.u32.u64 %0, t; }"
        : "=r"(a) : "l"(p));
    return a;
}

// ---------------- device scratch ----------------
__device__ float g_qkv[TOKENS * QKVD];
__device__ float g_qs [TOKENS * CDIM];
__device__ float g_qc [TOKENS * CDIM];
__device__ float g_knv[TOKENS * CDIM];
__device__ float g_kns[TOKENS * CDIM];
__device__ float g_kc [TOKENS * CDIM];
__device__ __nv_bfloat16 g_xh [TOKENS * CDIM];
__device__ __nv_bfloat16 g_xl [TOKENS * CDIM];
__device__ __nv_bfloat16 g_wqh[QKVD * CDIM];
__device__ __nv_bfloat16 g_wql[QKVD * CDIM];
__device__ __nv_bfloat16 g_wph[CDIM * CDIM];
__device__ __nv_bfloat16 g_wpl[CDIM * CDIM];
__device__ __nv_bfloat16 g_ath[TOKENS * CDIM];
__device__ __nv_bfloat16 g_atl[TOKENS * CDIM];

// ---------------------------------------------------------------------------
// Merged split of all three fp32 inputs -> bf16 hi/lo. (R9 proven)
// ---------------------------------------------------------------------------
#define NX (TOKENS * CDIM)
#define NQ (QKVD * CDIM)
#define NP (CDIM * CDIM)
__global__ __launch_bounds__(256)
void split_all(const float* __restrict__ x, const float* __restrict__ wq,
               const float* __restrict__ wp,
               __nv_bfloat16* __restrict__ xh, __nv_bfloat16* __restrict__ xl,
               __nv_bfloat16* __restrict__ wqh, __nv_bfloat16* __restrict__ wql,
               __nv_bfloat16* __restrict__ wph, __nv_bfloat16* __restrict__ wpl)
{
    int i = blockIdx.x * 256 + threadIdx.x;
    const float* src; __nv_bfloat16 *h, *l; int off;
    if (i < NX)           { src = x;  h = xh;  l = xl;  off = i; }
    else if (i < NX + NQ) { src = wq; h = wqh; l = wql; off = i - NX; }
    else                  { src = wp; h = wph; l = wpl; off = i - NX - NQ; }
    float v = src[off];
    __nv_bfloat16 hh = __float2bfloat16(v);
    h[off] = hh;
    l[off] = __float2bfloat16(v - __bfloat162float(hh));
}

// ---------------------------------------------------------------------------
// HMMA split-bf16 GEMM (R8 proven, unchanged).
// ---------------------------------------------------------------------------
#define GS       144
#define OFF_AL   9216
#define OFF_BH   18432
#define OFF_BL   27648
#define BUFSZ    36864
#define HG_SMEM  (2 * BUFSZ)

__device__ __forceinline__ void mma_bf16(float* c, const uint32_t* a,
                                         const uint32_t* b) {
    asm volatile(
        "mma.sync.aligned.m16n8k16.row.col.f32.bf16.bf16.f32 "
        "{%0,%1,%2,%3}, {%4,%5,%6,%7}, {%8,%9}, {%0,%1,%2,%3};"
        : "+f"(c[0]), "+f"(c[1]), "+f"(c[2]), "+f"(c[3])
        : "r"(a[0]), "r"(a[1]), "r"(a[2]), "r"(a[3]), "r"(b[0]), "r"(b[1]));
}
__device__ __forceinline__ void cp16(uint32_t s, const void* g) {
    asm volatile("cp.async.cg.shared.global [%0], [%1], 16;" :: "r"(s), "l"(g));
}
__device__ __forceinline__ uint32_t lds32(uint32_t a) {
    uint32_t v; asm("ld.shared.b32 %0,[%1];" : "=r"(v) : "r"(a)); return v;
}

__global__ __launch_bounds__(128)
void hmma_gemm(const __nv_bfloat16* __restrict__ Ah, const __nv_bfloat16* __restrict__ Al,
               const __nv_bfloat16* __restrict__ Bh, const __nv_bfloat16* __restrict__ Bl,
               const float* __restrict__ bias, float* __restrict__ C, int Ncols)
{
    extern __shared__ char smem[];
    const uint32_t sb = smem_u32(smem);
    const int tid = threadIdx.x;
    const int w = tid >> 5, lane = tid & 31;
    const int g = lane >> 2, tg = lane & 3;
    const int m0 = blockIdx.y * 64, n0 = blockIdx.x * 64;
    const int wm = (w >> 1) * 32, wn = (w & 1) * 32;

    float acc[2][4][4];
    #pragma unroll
    for (int mt = 0; mt < 2; mt++)
        #pragma unroll
        for (int nt = 0; nt < 4; nt++)
            #pragma unroll
            for (int i = 0; i < 4; i++) acc[mt][nt][i] = 0.f;

    #define ISSUE_CHUNK(cc, pp) do {                                          \
        int k0_ = (cc) * 64;                                                  \
        uint32_t dst_ = sb + (pp) * BUFSZ;                                    \
        _Pragma("unroll")                                                     \
        for (int v_ = 0; v_ < 4; v_++) {                                      \
            int f_ = v_ * 128 + tid;                                          \
            int row_ = f_ >> 3, cg_ = f_ & 7;                                 \
            uint32_t so_ = row_ * GS + cg_ * 16;                              \
            size_t ga_ = (size_t)(m0 + row_) * CDIM + k0_ + cg_ * 8;          \
            size_t gb_ = (size_t)(n0 + row_) * CDIM + k0_ + cg_ * 8;          \
            cp16(dst_ + so_,          Ah + ga_);                              \
            cp16(dst_ + OFF_AL + so_, Al + ga_);                              \
            cp16(dst_ + OFF_BH + so_, Bh + gb_);                              \
            cp16(dst_ + OFF_BL + so_, Bl + gb_);                              \
        }                                                                     \
        asm volatile("cp.async.commit_group;");                               \
    } while (0)

    ISSUE_CHUNK(0, 0);
    ISSUE_CHUNK(1, 1);

    for (int c = 0; c < 8; ++c) {
        if (c == 7) asm volatile("cp.async.wait_group 0;" ::: "memory");
        else        asm volatile("cp.async.wait_group 1;" ::: "memory");
        __syncthreads();

        const uint32_t buf = sb + (c & 1) * BUFSZ;
        #pragma unroll
        for (int ks = 0; ks < 4; ks++) {
            uint32_t aH[2][4], aL[2][4], bH[4][2], bL[4][2];
            #pragma unroll
            for (int mt = 0; mt < 2; mt++) {
                uint32_t ad = buf + (wm + mt * 16 + g) * GS + ks * 32 + tg * 4;
                aH[mt][0] = lds32(ad);
                aH[mt][1] = lds32(ad + 8 * GS);
                aH[mt][2] = lds32(ad + 16);
                aH[mt][3] = lds32(ad + 8 * GS + 16);
                uint32_t al = ad + OFF_AL;
                aL[mt][0] = lds32(al);
                aL[mt][1] = lds32(al + 8 * GS);
                aL[mt][2] = lds32(al + 16);
                aL[mt][3] = lds32(al + 8 * GS + 16);
            }
            #pragma unroll
            for (int nt = 0; nt < 4; nt++) {
                uint32_t bd = buf + OFF_BH + (wn + nt * 8 + g) * GS + ks * 32 + tg * 4;
                bH[nt][0] = lds32(bd);
                bH[nt][1] = lds32(bd + 16);
                uint32_t bl = bd + (OFF_BL - OFF_BH);
                bL[nt][0] = lds32(bl);
                bL[nt][1] = lds32(bl + 16);
            }
            #pragma unroll
            for (int mt = 0; mt < 2; mt++)
                #pragma unroll
                for (int nt = 0; nt < 4; nt++) {
                    mma_bf16(acc[mt][nt], aH[mt], bH[nt]);
                    mma_bf16(acc[mt][nt], aH[mt], bL[nt]);
                    mma_bf16(acc[mt][nt], aL[mt], bH[nt]);
                }
        }
        __syncthreads();
        if (c + 2 < 8) ISSUE_CHUNK(c + 2, c & 1);
    }

    #pragma unroll
    for (int mt = 0; mt < 2; mt++) {
        int r0 = m0 + wm + mt * 16 + g;
        #pragma unroll
        for (int nt = 0; nt < 4; nt++) {
            int col = n0 + wn + nt * 8 + tg * 2;
            float b0 = 0.f, b1 = 0.f;
            if (bias) { b0 = bias[col]; b1 = bias[col + 1]; }
            *(float2*)&C[(size_t)r0 * Ncols + col] =
                make_float2(acc[mt][nt][0] + b0, acc[mt][nt][1] + b1);
            *(float2*)&C[(size_t)(r0 + 8) * Ncols + col] =
                make_float2(acc[mt][nt][2] + b0, acc[mt][nt][3] + b1);
        }
    }
    #undef ISSUE_CHUNK
}

// ---------------------------------------------------------------------------
// Trig precompute (unchanged).
// ---------------------------------------------------------------------------
__global__ __launch_bounds__(256)
void trig_prep(const float* __restrict__ qkv, const float* __restrict__ paramR,
               float* __restrict__ gqs, float* __restrict__ gqc,
               float* __restrict__ gknv, float* __restrict__ gkns,
               float* __restrict__ gkc)
{
    int i = blockIdx.x * 256 + threadIdx.x;
    const float R = paramR[0];
    int tok = i >> 9, col = i & 511;
    float qv = qkv[tok * QKVD + col];
    float s, c;
    sincosf(R * qv, &s, &c);
    gqs[i] = s; gqc[i] = c;
    float kv = qkv[tok * QKVD + CDIM + col];
    sincosf(R * kv, &s, &c);
    gknv[i] = -kv; gkns[i] = -s; gkc[i] = c;
}

// ---------------------------------------------------------------------------
// Fourier attention, two-phase per 32-key tile for occupancy (3 blocks/SM).
// Block = (qtile, head, batch), 256 threads: q = tid&31, kg = tid>>5.
// Phase A: thread scores its 4 keys over all 64 dims -> a4 in sS[32][33].
// Phase B: thread accumulates PV for its 8-dim slice over the 32 keys
//          (acc[4] u64 = 8 regs instead of 64). No end-of-kernel stash.
// ---------------------------------------------------------------------------
#define KT2   32
static const int ATTN_SMEM = (3 * 16 * CH + 4 * KT2 * DH + KT2 * 33 + 8 * QT) * 4;

__global__ __launch_bounds__(256, 3)
void fourier_attn5(const float* __restrict__ qkv,
                   const float* __restrict__ gqs, const float* __restrict__ gqc,
                   const float* __restrict__ gknv, const float* __restrict__ gkns,
                   const float* __restrict__ gkc,
                   const float* __restrict__ paramR,
                   __nv_bfloat16* __restrict__ outh,
                   __nv_bfloat16* __restrict__ outl)
{
    extern __shared__ float sm[];
    float* sQv = sm;                         // [16][CH]
    float* sQs = sQv + 16 * CH;
    float* sQc = sQs + 16 * CH;
    float* sKv = sQc + 16 * CH;              // [32][64]
    float* sKs = sKv + KT2 * DH;
    float* sKc = sKs + KT2 * DH;
    float* sV  = sKc + KT2 * DH;
    float* sS  = sV  + KT2 * DH;             // [32][33] a4
    float* sRed = sS + KT2 * 33;             // [8][32]

    const int tid = threadIdx.x;
    const int q = tid & 31, kg = tid >> 5;
    const int qt = blockIdx.x, h = blockIdx.y, b = blockIdx.z;
    const int tok0 = b * NSEQ, q0 = qt * QT;
    const float R = paramR[0];

    // q-side fill: chunked [d4][q][4]
    for (int i = tid; i < QT * 16; i += 256) {
        int d4 = i & 15, qq = i >> 4;
        int g = (tok0 + q0 + qq) * CDIM + h * DH + d4 * 4;
        int sidx = d4 * CH + qq * 4;
        *(float4*)&sQs[sidx] = *(const float4*)&gqs[g];
        *(float4*)&sQc[sidx] = *(const float4*)&gqc[g];
        *(float4*)&sQv[sidx] = *(const float4*)&qkv[(tok0 + q0 + qq) * QKVD + h * DH + d4 * 4];
    }

    u64 acc[4];
    #pragma unroll
    for (int i = 0; i < 4; i++) acc[i] = 0ull;
    float rowsum = 0.f;

    for (int t = 0; t < NSEQ / KT2; ++t) {
        __syncthreads();                          // prior phase B done
        for (int i = tid; i < KT2 * 16; i += 256) {
            int kk = i >> 4, dq = (i & 15) * 4;
            int g = (tok0 + t * KT2 + kk) * CDIM + h * DH + dq;
            int sidx = kk * DH + dq;
            *(float4*)&sKv[sidx] = *(const float4*)&gknv[g];
            *(float4*)&sKs[sidx] = *(const float4*)&gkns[g];
            *(float4*)&sKc[sidx] = *(const float4*)&gkc[g];
            *(float4*)&sV[sidx]  = *(const float4*)&qkv[(tok0 + t * KT2 + kk) * QKVD + 2 * CDIM + h * DH + dq];
        }
        __syncthreads();

        // ---- phase A: scores for this thread's 4 keys ----
        float np[4], dp[4];
        #pragma unroll
        for (int j = 0; j < 4; j++) { np[j] = 1.f; dp[j] = 1.f; }
        const int kb0 = kg * 4 * DH;

        #pragma unroll 2
        for (int d4 = 0; d4 < 16; d4++) {
            int qidx = d4 * CH + q * 4;
            ulonglong2 qv = *(const ulonglong2*)&sQv[qidx];
            ulonglong2 qs = *(const ulonglong2*)&sQs[qidx];
            ulonglong2 qc = *(const ulonglong2*)&sQc[qidx];
            #pragma unroll
            for (int j = 0; j < 4; j++) {
                int koff = kb0 + j * DH + d4 * 4;
                ulonglong2 kv = *(const ulonglong2*)&sKv[koff];
                ulonglong2 ks = *(const ulonglong2*)&sKs[koff];
                ulonglong2 kc = *(const ulonglong2*)&sKc[koff];
                u64 dfa = fadd2(qv.x, kv.x);
                u64 dfb = fadd2(qv.y, kv.y);
                u64 nma = ffma2(qs.x, kc.x, fmul2(qc.x, ks.x));
                u64 nmb = ffma2(qs.y, kc.y, fmul2(qc.y, ks.y));
                float d0, d1, d2, d3, n0, n1, n2, n3;
                up2(dfa, d0, d1); up2(dfb, d2, d3);
                up2(nma, n0, n1); up2(nmb, n2, n3);
                bool s0 = fabsf(d0) < T_SMALL, s1 = fabsf(d1) < T_SMALL;
                bool s2 = fabsf(d2) < T_SMALL, s3 = fabsf(d3) < T_SMALL;
                np[j] *= s0 ? R : n0;  dp[j] *= s0 ? 1.f : d0;
                np[j] *= s1 ? R : n1;  dp[j] *= s1 ? 1.f : d1;
                np[j] *= s2 ? R : n2;  dp[j] *= s2 ? 1.f : d2;
                np[j] *= s3 ? R : n3;  dp[j] *= s3 ? 1.f : d3;
            }
        }
        #pragma unroll
        for (int j = 0; j < 4; j++) {
            float s = (dp[j] != 0.f) ? np[j] / dp[j] : 0.f;
            float s2 = s * s;
            float a4 = s2 * s2;
            rowsum += a4;
            sS[(kg * 4 + j) * 33 + q] = a4;
        }
        __syncthreads();

        // ---- phase B: PV for this thread's 8-dim slice over 32 keys ----
        #pragma unroll 8
        for (int j = 0; j < KT2; j++) {
            float a = sS[j * 33 + q];
            u64 aa = pk2(a, a);
            const ulonglong2* vp = (const ulonglong2*)&sV[j * DH + kg * 8];
            ulonglong2 v0 = vp[0], v1 = vp[1];
            acc[0] = ffma2(aa, v0.x, acc[0]);
            acc[1] = ffma2(aa, v0.y, acc[1]);
            acc[2] = ffma2(aa, v1.x, acc[2]);
            acc[3] = ffma2(aa, v1.y, acc[3]);
        }
    }
    __syncthreads();

    sRed[kg * 32 + q] = rowsum;
    __syncthreads();
    float ss = 0.f;
    #pragma unroll
    for (int r = 0; r < 8; r++) ss += sRed[r * 32 + q];
    float inv = 1.f / (ss + EPSF);
    u64 inv2 = pk2(inv, inv);

    #pragma unroll
    for (int i = 0; i < 4; i++) acc[i] = fmul2(acc[i], inv2);

    float of[8];
    up2(acc[0], of[0], of[1]); up2(acc[1], of[2], of[3]);
    up2(acc[2], of[4], of[5]); up2(acc[3], of[6], of[7]);

    __nv_bfloat16 hb[8], lb[8];
    #pragma unroll
    for (int i = 0; i < 8; i++) {
        __nv_bfloat16 hh = __float2bfloat16(of[i]);
        hb[i] = hh;
        lb[i] = __float2bfloat16(of[i] - __bfloat162float(hh));
    }
    size_t base = (size_t)(tok0 + q0 + q) * CDIM + h * DH + kg * 8;
    *(uint4*)&outh[base] = *(const uint4*)hb;
    *(uint4*)&outl[base] = *(const uint4*)lb;
}

extern "C" void kernel_launch(void* const* d_in, const int* in_sizes, int n_in,
                              void* d_out, int out_size)
{
    const float* x      = (const float*)d_in[0];
    const float* w_qkv  = (const float*)d_in[1];
    const float* w_proj = (const float*)d_in[2];
    const float* b_proj = (const float*)d_in[3];
    const float* paramR = (const float*)d_in[4];
    float* out = (float*)d_out;

    float *qkvbuf, *gqs, *gqc, *gknv, *gkns, *gkc;
    __nv_bfloat16 *xh, *xl, *wqh, *wql, *wph, *wpl, *ath, *atl;
    cudaGetSymbolAddress((void**)&qkvbuf, g_qkv);
    cudaGetSymbolAddress((void**)&gqs,  g_qs);
    cudaGetSymbolAddress((void**)&gqc,  g_qc);
    cudaGetSymbolAddress((void**)&gknv, g_knv);
    cudaGetSymbolAddress((void**)&gkns, g_kns);
    cudaGetSymbolAddress((void**)&gkc,  g_kc);
    cudaGetSymbolAddress((void**)&xh,  g_xh);
    cudaGetSymbolAddress((void**)&xl,  g_xl);
    cudaGetSymbolAddress((void**)&wqh, g_wqh);
    cudaGetSymbolAddress((void**)&wql, g_wql);
    cudaGetSymbolAddress((void**)&wph, g_wph);
    cudaGetSymbolAddress((void**)&wpl, g_wpl);
    cudaGetSymbolAddress((void**)&ath, g_ath);
    cudaGetSymbolAddress((void**)&atl, g_atl);

    cudaFuncSetAttribute(fourier_attn5, cudaFuncAttributeMaxDynamicSharedMemorySize,
                         ATTN_SMEM);
    cudaFuncSetAttribute(hmma_gemm, cudaFuncAttributeMaxDynamicSharedMemorySize,
                         HG_SMEM);

    // 0) merged split of fp32 inputs to bf16 hi/lo
    split_all<<<(NX + NQ + NP) / 256, 256>>>(x, w_qkv, w_proj,
                                             xh, xl, wqh, wql, wph, wpl);

    // 1) qkv = x @ w_qkv^T via HMMA (384 CTAs)
    hmma_gemm<<<dim3(QKVD / 64, TOKENS / 64), 128, HG_SMEM>>>(
        xh, xl, wqh, wql, nullptr, qkvbuf, QKVD);

    // 2) trig precompute
    trig_prep<<<TOKENS * CDIM / 256, 256>>>(qkvbuf, paramR, gqs, gqc, gknv, gkns, gkc);

    // 3) two-phase attention (256 blocks, 3/SM)
    fourier_attn5<<<dim3(NSEQ / QT, HEADS, 4), 256, ATTN_SMEM>>>(
        qkvbuf, gqs, gqc, gknv, gkns, gkc, paramR, ath, atl);

    // 4) proj via HMMA (128 CTAs)
    hmma_gemm<<<dim3(CDIM / 64, TOKENS / 64), 128, HG_SMEM>>>(
        ath, atl, wph, wpl, b_proj, out, CDIM);
}

// round 11
// speedup vs baseline: 1.1612x; 1.1612x over previous
#include <cuda_runtime.h>
#include <cuda_bf16.h>
#include <math.h>
#include <stdint.h>

typedef unsigned long long u64;

#define TOKENS 1024
#define CDIM   512
#define QKVD   1536
#define NSEQ   256
#define HEADS  8
#define DH     64
#define QT     32
#define EPSF   1e-6f
#define CH     132                      // q-side chunk stride (floats)

// ---------------- packed f32x2 helpers ----------------
__device__ __forceinline__ u64 pk2(float lo, float hi) {
    u64 r; asm("mov.b64 %0,{%1,%2};" : "=l"(r) : "f"(lo), "f"(hi)); return r;
}
__device__ __forceinline__ void up2(u64 v, float& lo, float& hi) {
    asm("mov.b64 {%0,%1},%2;" : "=f"(lo), "=f"(hi) : "l"(v));
}
__device__ __forceinline__ u64 fadd2(u64 a, u64 b) {
    u64 r; asm("add.rn.f32x2 %0,%1,%2;" : "=l"(r) : "l"(a), "l"(b)); return r;
}
__device__ __forceinline__ u64 fmul2(u64 a, u64 b) {
    u64 r; asm("mul.rn.f32x2 %0,%1,%2;" : "=l"(r) : "l"(a), "l"(b)); return r;
}
__device__ __forceinline__ u64 ffma2(u64 a, u64 b, u64 c) {
    u64 r; asm("fma.rn.f32x2 %0,%1,%2,%3;" : "=l"(r) : "l"(a), "l"(b), "l"(c)); return r;
}
__device__ __forceinline__ uint32_t smem_u32(const void* p) {
    uint32_t a;
    asm("{ .reg .u64 t; cvta.to.shared.u64 t, %1; cvt.u32.u64 %0, t; }"
        : "=r"(a) : "l"(p));
    return a;
}

// ---------------- device scratch ----------------
__device__ float g_qkv[TOKENS * QKVD];
__device__ __nv_bfloat16 g_xh [TOKENS * CDIM];
__device__ __nv_bfloat16 g_xl [TOKENS * CDIM];
__device__ __nv_bfloat16 g_wqh[QKVD * CDIM];
__device__ __nv_bfloat16 g_wql[QKVD * CDIM];
__device__ __nv_bfloat16 g_wph[CDIM * CDIM];
__device__ __nv_bfloat16 g_wpl[CDIM * CDIM];
__device__ __nv_bfloat16 g_ath[TOKENS * CDIM];
__device__ __nv_bfloat16 g_atl[TOKENS * CDIM];

// ---------------------------------------------------------------------------
// Merged split of all three fp32 inputs -> bf16 hi/lo. (proven)
// ---------------------------------------------------------------------------
#define NX (TOKENS * CDIM)
#define NQ (QKVD * CDIM)
#define NP (CDIM * CDIM)
__global__ __launch_bounds__(256)
void split_all(const float* __restrict__ x, const float* __restrict__ wq,
               const float* __restrict__ wp,
               __nv_bfloat16* __restrict__ xh, __nv_bfloat16* __restrict__ xl,
               __nv_bfloat16* __restrict__ wqh, __nv_bfloat16* __restrict__ wql,
               __nv_bfloat16* __restrict__ wph, __nv_bfloat16* __restrict__ wpl)
{
    int i = blockIdx.x * 256 + threadIdx.x;
    const float* src; __nv_bfloat16 *h, *l; int off;
    if (i < NX)           { src = x;  h = xh;  l = xl;  off = i; }
    else if (i < NX + NQ) { src = wq; h = wqh; l = wql; off = i - NX; }
    else                  { src = wp; h = wph; l = wpl; off = i - NX - NQ; }
    float v = src[off];
    __nv_bfloat16 hh = __float2bfloat16(v);
    h[off] = hh;
    l[off] = __float2bfloat16(v - __bfloat162float(hh));
}

// ---------------------------------------------------------------------------
// HMMA split-bf16 GEMM (R8 proven, unchanged).
// ---------------------------------------------------------------------------
#define GS       144
#define OFF_AL   9216
#define OFF_BH   18432
#define OFF_BL   27648
#define BUFSZ    36864
#define HG_SMEM  (2 * BUFSZ)

__device__ __forceinline__ void mma_bf16(float* c, const uint32_t* a,
                                         const uint32_t* b) {
    asm volatile(
        "mma.sync.aligned.m16n8k16.row.col.f32.bf16.bf16.f32 "
        "{%0,%1,%2,%3}, {%4,%5,%6,%7}, {%8,%9}, {%0,%1,%2,%3};"
        : "+f"(c[0]), "+f"(c[1]), "+f"(c[2]), "+f"(c[3])
        : "r"(a[0]), "r"(a[1]), "r"(a[2]), "r"(a[3]), "r"(b[0]), "r"(b[1]));
}
__device__ __forceinline__ void cp16(uint32_t s, const void* g) {
    asm volatile("cp.async.cg.shared.global [%0], [%1], 16;" :: "r"(s), "l"(g));
}
__device__ __forceinline__ uint32_t lds32(uint32_t a) {
    uint32_t v; asm("ld.shared.b32 %0,[%1];" : "=r"(v) : "r"(a)); return v;
}

__global__ __launch_bounds__(128)
void hmma_gemm(const __nv_bfloat16* __restrict__ Ah, const __nv_bfloat16* __restrict__ Al,
               const __nv_bfloat16* __restrict__ Bh, const __nv_bfloat16* __restrict__ Bl,
               const float* __restrict__ bias, float* __restrict__ C, int Ncols)
{
    extern __shared__ char smem[];
    const uint32_t sb = smem_u32(smem);
    const int tid = threadIdx.x;
    const int w = tid >> 5, lane = tid & 31;
    const int g = lane >> 2, tg = lane & 3;
    const int m0 = blockIdx.y * 64, n0 = blockIdx.x * 64;
    const int wm = (w >> 1) * 32, wn = (w & 1) * 32;

    float acc[2][4][4];
    #pragma unroll
    for (int mt = 0; mt < 2; mt++)
        #pragma unroll
        for (int nt = 0; nt < 4; nt++)
            #pragma unroll
            for (int i = 0; i < 4; i++) acc[mt][nt][i] = 0.f;

    #define ISSUE_CHUNK(cc, pp) do {                                          \
        int k0_ = (cc) * 64;                                                  \
        uint32_t dst_ = sb + (pp) * BUFSZ;                                    \
        _Pragma("unroll")                                                     \
        for (int v_ = 0; v_ < 4; v_++) {                                      \
            int f_ = v_ * 128 + tid;                                          \
            int row_ = f_ >> 3, cg_ = f_ & 7;                                 \
            uint32_t so_ = row_ * GS + cg_ * 16;                              \
            size_t ga_ = (size_t)(m0 + row_) * CDIM + k0_ + cg_ * 8;          \
            size_t gb_ = (size_t)(n0 + row_) * CDIM + k0_ + cg_ * 8;          \
            cp16(dst_ + so_,          Ah + ga_);                              \
            cp16(dst_ + OFF_AL + so_, Al + ga_);                              \
            cp16(dst_ + OFF_BH + so_, Bh + gb_);                              \
            cp16(dst_ + OFF_BL + so_, Bl + gb_);                              \
        }                                                                     \
        asm volatile("cp.async.commit_group;");                               \
    } while (0)

    ISSUE_CHUNK(0, 0);
    ISSUE_CHUNK(1, 1);

    for (int c = 0; c < 8; ++c) {
        if (c == 7) asm volatile("cp.async.wait_group 0;" ::: "memory");
        else        asm volatile("cp.async.wait_group 1;" ::: "memory");
        __syncthreads();

        const uint32_t buf = sb + (c & 1) * BUFSZ;
        #pragma unroll
        for (int ks = 0; ks < 4; ks++) {
            uint32_t aH[2][4], aL[2][4], bH[4][2], bL[4][2];
            #pragma unroll
            for (int mt = 0; mt < 2; mt++) {
                uint32_t ad = buf + (wm + mt * 16 + g) * GS + ks * 32 + tg * 4;
                aH[mt][0] = lds32(ad);
                aH[mt][1] = lds32(ad + 8 * GS);
                aH[mt][2] = lds32(ad + 16);
                aH[mt][3] = lds32(ad + 8 * GS + 16);
                uint32_t al = ad + OFF_AL;
                aL[mt][0] = lds32(al);
                aL[mt][1] = lds32(al + 8 * GS);
                aL[mt][2] = lds32(al + 16);
                aL[mt][3] = lds32(al + 8 * GS + 16);
            }
            #pragma unroll
            for (int nt = 0; nt < 4; nt++) {
                uint32_t bd = buf + OFF_BH + (wn + nt * 8 + g) * GS + ks * 32 + tg * 4;
                bH[nt][0] = lds32(bd);
                bH[nt][1] = lds32(bd + 16);
                uint32_t bl = bd + (OFF_BL - OFF_BH);
                bL[nt][0] = lds32(bl);
                bL[nt][1] = lds32(bl + 16);
            }
            #pragma unroll
            for (int mt = 0; mt < 2; mt++)
                #pragma unroll
                for (int nt = 0; nt < 4; nt++) {
                    mma_bf16(acc[mt][nt], aH[mt], bH[nt]);
                    mma_bf16(acc[mt][nt], aH[mt], bL[nt]);
                    mma_bf16(acc[mt][nt], aL[mt], bH[nt]);
                }
        }
        __syncthreads();
        if (c + 2 < 8) ISSUE_CHUNK(c + 2, c & 1);
    }

    #pragma unroll
    for (int mt = 0; mt < 2; mt++) {
        int r0 = m0 + wm + mt * 16 + g;
        #pragma unroll
        for (int nt = 0; nt < 4; nt++) {
            int col = n0 + wn + nt * 8 + tg * 2;
            float b0 = 0.f, b1 = 0.f;
            if (bias) { b0 = bias[col]; b1 = bias[col + 1]; }
            *(float2*)&C[(size_t)r0 * Ncols + col] =
                make_float2(acc[mt][nt][0] + b0, acc[mt][nt][1] + b1);
            *(float2*)&C[(size_t)(r0 + 8) * Ncols + col] =
                make_float2(acc[mt][nt][2] + b0, acc[mt][nt][3] + b1);
        }
    }
    #undef ISSUE_CHUNK
}

// ---------------------------------------------------------------------------
// Fourier attention, MUFU-sin formulation. Two-phase per 32-key tile.
// score factor: s_d = sin(R*(q-k)) / (q-k), with sin computed DIRECTLY from
// the difference via __sinf (MUFU.SIN) -> no cancellation, no per-dim selects.
// np2/dp2 are packed f32x2 product chains over even/odd dims. Exact d==0
// gives np=dp=0 -> caught by the key-level dp!=0 guard (s=0), same as shipped.
// Phase B (PV over 8-dim slice) unchanged from R10.
// ---------------------------------------------------------------------------
#define KT2   32
static const int ATTN_SMEM = (16 * CH + 2 * KT2 * DH + KT2 * 33 + 8 * QT) * 4;

__global__ __launch_bounds__(256, 3)
void fourier_attn6(const float* __restrict__ qkv,
                   const float* __restrict__ paramR,
                   __nv_bfloat16* __restrict__ outh,
                   __nv_bfloat16* __restrict__ outl)
{
    extern __shared__ float sm[];
    float* sQv = sm;                         // [16][CH] chunked q values
    float* sKv = sQv + 16 * CH;              // [32][64] NEGATED k values
    float* sV  = sKv + KT2 * DH;             // [32][64]
    float* sS  = sV  + KT2 * DH;             // [32][33] a4
    float* sRed = sS + KT2 * 33;             // [8][32]

    const int tid = threadIdx.x;
    const int q = tid & 31, kg = tid >> 5;
    const int qt = blockIdx.x, h = blockIdx.y, b = blockIdx.z;
    const int tok0 = b * NSEQ, q0 = qt * QT;
    const float R = paramR[0];
    const u64 R2 = pk2(R, R);

    // q-side fill: chunked [d4][q][4], values only
    for (int i = tid; i < QT * 16; i += 256) {
        int d4 = i & 15, qq = i >> 4;
        *(float4*)&sQv[d4 * CH + qq * 4] =
            *(const float4*)&qkv[(tok0 + q0 + qq) * QKVD + h * DH + d4 * 4];
    }

    u64 acc[4];
    #pragma unroll
    for (int i = 0; i < 4; i++) acc[i] = 0ull;
    float rowsum = 0.f;

    for (int t = 0; t < NSEQ / KT2; ++t) {
        __syncthreads();
        for (int i = tid; i < KT2 * 16; i += 256) {
            int kk = i >> 4, dq = (i & 15) * 4;
            float4 kv = *(const float4*)&qkv[(tok0 + t * KT2 + kk) * QKVD + CDIM + h * DH + dq];
            *(float4*)&sKv[kk * DH + dq] = make_float4(-kv.x, -kv.y, -kv.z, -kv.w);
            *(float4*)&sV [kk * DH + dq] =
                *(const float4*)&qkv[(tok0 + t * KT2 + kk) * QKVD + 2 * CDIM + h * DH + dq];
        }
        __syncthreads();

        // ---- phase A: scores for this thread's 4 keys ----
        u64 np[4], dp[4];
        #pragma unroll
        for (int j = 0; j < 4; j++) { np[j] = pk2(1.f, 1.f); dp[j] = pk2(1.f, 1.f); }
        const int kb0 = kg * 4 * DH;

        #pragma unroll 4
        for (int d4 = 0; d4 < 16; d4++) {
            ulonglong2 qv = *(const ulonglong2*)&sQv[d4 * CH + q * 4];
            #pragma unroll
            for (int j = 0; j < 4; j++) {
                ulonglong2 kv = *(const ulonglong2*)&sKv[kb0 + j * DH + d4 * 4];
                u64 d01 = fadd2(qv.x, kv.x);            // q - k (dims 0,1)
                u64 d23 = fadd2(qv.y, kv.y);            // dims 2,3
                u64 rd01 = fmul2(R2, d01);
                u64 rd23 = fmul2(R2, d23);
                float a0, a1, a2, a3;
                up2(rd01, a0, a1); up2(rd23, a2, a3);
                float s0 = __sinf(a0), s1 = __sinf(a1);
                float s2 = __sinf(a2), s3 = __sinf(a3);
                np[j] = fmul2(np[j], pk2(s0, s1));
                np[j] = fmul2(np[j], pk2(s2, s3));
                dp[j] = fmul2(dp[j], d01);
                dp[j] = fmul2(dp[j], d23);
            }
        }
        #pragma unroll
        for (int j = 0; j < 4; j++) {
            float n0, n1, dd0, dd1;
            up2(np[j], n0, n1); up2(dp[j], dd0, dd1);
            float npp = n0 * n1, dpp = dd0 * dd1;
            float s = (dpp != 0.f) ? npp / dpp : 0.f;
            float s2 = s * s;
            float a4 = s2 * s2;
            rowsum += a4;
            sS[(kg * 4 + j) * 33 + q] = a4;
        }
        __syncthreads();

        // ---- phase B: PV for this thread's 8-dim slice over 32 keys ----
        #pragma unroll 8
        for (int j = 0; j < KT2; j++) {
            float a = sS[j * 33 + q];
            u64 aa = pk2(a, a);
            const ulonglong2* vp = (const ulonglong2*)&sV[j * DH + kg * 8];
            ulonglong2 v0 = vp[0], v1 = vp[1];
            acc[0] = ffma2(aa, v0.x, acc[0]);
            acc[1] = ffma2(aa, v0.y, acc[1]);
            acc[2] = ffma2(aa, v1.x, acc[2]);
            acc[3] = ffma2(aa, v1.y, acc[3]);
        }
    }
    __syncthreads();

    sRed[kg * 32 + q] = rowsum;
    __syncthreads();
    float ss = 0.f;
    #pragma unroll
    for (int r = 0; r < 8; r++) ss += sRed[r * 32 + q];
    float inv = 1.f / (ss + EPSF);
    u64 inv2 = pk2(inv, inv);

    #pragma unroll
    for (int i = 0; i < 4; i++) acc[i] = fmul2(acc[i], inv2);

    float of[8];
    up2(acc[0], of[0], of[1]); up2(acc[1], of[2], of[3]);
    up2(acc[2], of[4], of[5]); up2(acc[3], of[6], of[7]);

    __nv_bfloat16 hb[8], lb[8];
    #pragma unroll
    for (int i = 0; i < 8; i++) {
        __nv_bfloat16 hh = __float2bfloat16(of[i]);
        hb[i] = hh;
        lb[i] = __float2bfloat16(of[i] - __bfloat162float(hh));
    }
    size_t base = (size_t)(tok0 + q0 + q) * CDIM + h * DH + kg * 8;
    *(uint4*)&outh[base] = *(const uint4*)hb;
    *(uint4*)&outl[base] = *(const uint4*)lb;
}

extern "C" void kernel_launch(void* const* d_in, const int* in_sizes, int n_in,
                              void* d_out, int out_size)
{
    const float* x      = (const float*)d_in[0];
    const float* w_qkv  = (const float*)d_in[1];
    const float* w_proj = (const float*)d_in[2];
    const float* b_proj = (const float*)d_in[3];
    const float* paramR = (const float*)d_in[4];
    float* out = (float*)d_out;

    float *qkvbuf;
    __nv_bfloat16 *xh, *xl, *wqh, *wql, *wph, *wpl, *ath, *atl;
    cudaGetSymbolAddress((void**)&qkvbuf, g_qkv);
    cudaGetSymbolAddress((void**)&xh,  g_xh);
    cudaGetSymbolAddress((void**)&xl,  g_xl);
    cudaGetSymbolAddress((void**)&wqh, g_wqh);
    cudaGetSymbolAddress((void**)&wql, g_wql);
    cudaGetSymbolAddress((void**)&wph, g_wph);
    cudaGetSymbolAddress((void**)&wpl, g_wpl);
    cudaGetSymbolAddress((void**)&ath, g_ath);
    cudaGetSymbolAddress((void**)&atl, g_atl);

    cudaFuncSetAttribute(fourier_attn6, cudaFuncAttributeMaxDynamicSharedMemorySize,
                         ATTN_SMEM);
    cudaFuncSetAttribute(hmma_gemm, cudaFuncAttributeMaxDynamicSharedMemorySize,
                         HG_SMEM);

    // 0) merged split of fp32 inputs to bf16 hi/lo
    split_all<<<(NX + NQ + NP) / 256, 256>>>(x, w_qkv, w_proj,
                                             xh, xl, wqh, wql, wph, wpl);

    // 1) qkv = x @ w_qkv^T via HMMA (384 CTAs)
    hmma_gemm<<<dim3(QKVD / 64, TOKENS / 64), 128, HG_SMEM>>>(
        xh, xl, wqh, wql, nullptr, qkvbuf, QKVD);

    // 2) MUFU-sin attention (256 blocks) — no trig tables needed
    fourier_attn6<<<dim3(NSEQ / QT, HEADS, 4), 256, ATTN_SMEM>>>(
        qkvbuf, paramR, ath, atl);

    // 3) proj via HMMA (128 CTAs)
    hmma_gemm<<<dim3(CDIM / 64, TOKENS / 64), 128, HG_SMEM>>>(
        ath, atl, wph, wpl, b_proj, out, CDIM);
}

// round 12
// speedup vs baseline: 1.1847x; 1.0202x over previous
#include <cuda_runtime.h>
#include <cuda_bf16.h>
#include <math.h>
#include <stdint.h>

typedef unsigned long long u64;

#define TOKENS 1024
#define CDIM   512
#define QKVD   1536
#define NSEQ   256
#define HEADS  8
#define DH     64
#define QT     32
#define EPSF   1e-6f
#define CH     132                      // q-side chunk stride (floats)
#define KT2    32

// ---------------- packed f32x2 helpers ----------------
__device__ __forceinline__ u64 pk2(float lo, float hi) {
    u64 r; asm("mov.b64 %0,{%1,%2};" : "=l"(r) : "f"(lo), "f"(hi)); return r;
}
__device__ __forceinline__ void up2(u64 v, float& lo, float& hi) {
    asm("mov.b64 {%0,%1},%2;" : "=f"(lo), "=f"(hi) : "l"(v));
}
__device__ __forceinline__ u64 fadd2(u64 a, u64 b) {
    u64 r; asm("add.rn.f32x2 %0,%1,%2;" : "=l"(r) : "l"(a), "l"(b)); return r;
}
__device__ __forceinline__ u64 fmul2(u64 a, u64 b) {
    u64 r; asm("mul.rn.f32x2 %0,%1,%2;" : "=l"(r) : "l"(a), "l"(b)); return r;
}
__device__ __forceinline__ u64 ffma2(u64 a, u64 b, u64 c) {
    u64 r; asm("fma.rn.f32x2 %0,%1,%2,%3;" : "=l"(r) : "l"(a), "l"(b), "l"(c)); return r;
}
__device__ __forceinline__ uint32_t smem_u32(const void* p) {
    uint32_t a;
    asm("{ .reg .u64 t; cvta.to.shared.u64 t, %1; cvt.u32.u64 %0, t; }"
        : "=r"(a) : "l"(p));
    return a;
}
__device__ __forceinline__ void cp16(uint32_t s, const void* g) {
    asm volatile("cp.async.cg.shared.global [%0], [%1], 16;" :: "r"(s), "l"(g));
}
__device__ __forceinline__ uint32_t lds32(uint32_t a) {
    uint32_t v; asm("ld.shared.b32 %0,[%1];" : "=r"(v) : "r"(a)); return v;
}

// ---------------- device scratch ----------------
__device__ float g_qkv[TOKENS * QKVD];
__device__ __nv_bfloat16 g_xh [TOKENS * CDIM];
__device__ __nv_bfloat16 g_xl [TOKENS * CDIM];
__device__ __nv_bfloat16 g_wqh[QKVD * CDIM];
__device__ __nv_bfloat16 g_wql[QKVD * CDIM];
__device__ __nv_bfloat16 g_wph[CDIM * CDIM];
__device__ __nv_bfloat16 g_wpl[CDIM * CDIM];
__device__ __nv_bfloat16 g_ath[TOKENS * CDIM];
__device__ __nv_bfloat16 g_atl[TOKENS * CDIM];

// ---------------------------------------------------------------------------
// Merged split of all three fp32 inputs -> bf16 hi/lo. (proven)
// ---------------------------------------------------------------------------
#define NX (TOKENS * CDIM)
#define NQ (QKVD * CDIM)
#define NP (CDIM * CDIM)
__global__ __launch_bounds__(256)
void split_all(const float* __restrict__ x, const float* __restrict__ wq,
               const float* __restrict__ wp,
               __nv_bfloat16* __restrict__ xh, __nv_bfloat16* __restrict__ xl,
               __nv_bfloat16* __restrict__ wqh, __nv_bfloat16* __restrict__ wql,
               __nv_bfloat16* __restrict__ wph, __nv_bfloat16* __restrict__ wpl)
{
    int i = blockIdx.x * 256 + threadIdx.x;
    const float* src; __nv_bfloat16 *h, *l; int off;
    if (i < NX)           { src = x;  h = xh;  l = xl;  off = i; }
    else if (i < NX + NQ) { src = wq; h = wqh; l = wql; off = i - NX; }
    else                  { src = wp; h = wph; l = wpl; off = i - NX - NQ; }
    float v = src[off];
    __nv_bfloat16 hh = __float2bfloat16(v);
    h[off] = hh;
    l[off] = __float2bfloat16(v - __bfloat162float(hh));
}

// ---------------------------------------------------------------------------
// HMMA split-bf16 GEMM (R8 proven, unchanged).
// ---------------------------------------------------------------------------
#define GS       144
#define OFF_AL   9216
#define OFF_BH   18432
#define OFF_BL   27648
#define BUFSZ    36864
#define HG_SMEM  (2 * BUFSZ)

__device__ __forceinline__ void mma_bf16(float* c, const uint32_t* a,
                                         const uint32_t* b) {
    asm volatile(
        "mma.sync.aligned.m16n8k16.row.col.f32.bf16.bf16.f32 "
        "{%0,%1,%2,%3}, {%4,%5,%6,%7}, {%8,%9}, {%0,%1,%2,%3};"
        : "+f"(c[0]), "+f"(c[1]), "+f"(c[2]), "+f"(c[3])
        : "r"(a[0]), "r"(a[1]), "r"(a[2]), "r"(a[3]), "r"(b[0]), "r"(b[1]));
}

__global__ __launch_bounds__(128)
void hmma_gemm(const __nv_bfloat16* __restrict__ Ah, const __nv_bfloat16* __restrict__ Al,
               const __nv_bfloat16* __restrict__ Bh, const __nv_bfloat16* __restrict__ Bl,
               const float* __restrict__ bias, float* __restrict__ C, int Ncols)
{
    extern __shared__ char smem[];
    const uint32_t sb = smem_u32(smem);
    const int tid = threadIdx.x;
    const int w = tid >> 5, lane = tid & 31;
    const int g = lane >> 2, tg = lane & 3;
    const int m0 = blockIdx.y * 64, n0 = blockIdx.x * 64;
    const int wm = (w >> 1) * 32, wn = (w & 1) * 32;

    float acc[2][4][4];
    #pragma unroll
    for (int mt = 0; mt < 2; mt++)
        #pragma unroll
        for (int nt = 0; nt < 4; nt++)
            #pragma unroll
            for (int i = 0; i < 4; i++) acc[mt][nt][i] = 0.f;

    #define ISSUE_CHUNK(cc, pp) do {                                          \
        int k0_ = (cc) * 64;                                                  \
        uint32_t dst_ = sb + (pp) * BUFSZ;                                    \
        _Pragma("unroll")                                                     \
        for (int v_ = 0; v_ < 4; v_++) {                                      \
            int f_ = v_ * 128 + tid;                                          \
            int row_ = f_ >> 3, cg_ = f_ & 7;                                 \
            uint32_t so_ = row_ * GS + cg_ * 16;                              \
            size_t ga_ = (size_t)(m0 + row_) * CDIM + k0_ + cg_ * 8;          \
            size_t gb_ = (size_t)(n0 + row_) * CDIM + k0_ + cg_ * 8;          \
            cp16(dst_ + so_,          Ah + ga_);                              \
            cp16(dst_ + OFF_AL + so_, Al + ga_);                              \
            cp16(dst_ + OFF_BH + so_, Bh + gb_);                              \
            cp16(dst_ + OFF_BL + so_, Bl + gb_);                              \
        }                                                                     \
        asm volatile("cp.async.commit_group;");                               \
    } while (0)

    ISSUE_CHUNK(0, 0);
    ISSUE_CHUNK(1, 1);

    for (int c = 0; c < 8; ++c) {
        if (c == 7) asm volatile("cp.async.wait_group 0;" ::: "memory");
        else        asm volatile("cp.async.wait_group 1;" ::: "memory");
        __syncthreads();

        const uint32_t buf = sb + (c & 1) * BUFSZ;
        #pragma unroll
        for (int ks = 0; ks < 4; ks++) {
            uint32_t aH[2][4], aL[2][4], bH[4][2], bL[4][2];
            #pragma unroll
            for (int mt = 0; mt < 2; mt++) {
                uint32_t ad = buf + (wm + mt * 16 + g) * GS + ks * 32 + tg * 4;
                aH[mt][0] = lds32(ad);
                aH[mt][1] = lds32(ad + 8 * GS);
                aH[mt][2] = lds32(ad + 16);
                aH[mt][3] = lds32(ad + 8 * GS + 16);
                uint32_t al = ad + OFF_AL;
                aL[mt][0] = lds32(al);
                aL[mt][1] = lds32(al + 8 * GS);
                aL[mt][2] = lds32(al + 16);
                aL[mt][3] = lds32(al + 8 * GS + 16);
            }
            #pragma unroll
            for (int nt = 0; nt < 4; nt++) {
                uint32_t bd = buf + OFF_BH + (wn + nt * 8 + g) * GS + ks * 32 + tg * 4;
                bH[nt][0] = lds32(bd);
                bH[nt][1] = lds32(bd + 16);
                uint32_t bl = bd + (OFF_BL - OFF_BH);
                bL[nt][0] = lds32(bl);
                bL[nt][1] = lds32(bl + 16);
            }
            #pragma unroll
            for (int mt = 0; mt < 2; mt++)
                #pragma unroll
                for (int nt = 0; nt < 4; nt++) {
                    mma_bf16(acc[mt][nt], aH[mt], bH[nt]);
                    mma_bf16(acc[mt][nt], aH[mt], bL[nt]);
                    mma_bf16(acc[mt][nt], aL[mt], bH[nt]);
                }
        }
        __syncthreads();
        if (c + 2 < 8) ISSUE_CHUNK(c + 2, c & 1);
    }

    #pragma unroll
    for (int mt = 0; mt < 2; mt++) {
        int r0 = m0 + wm + mt * 16 + g;
        #pragma unroll
        for (int nt = 0; nt < 4; nt++) {
            int col = n0 + wn + nt * 8 + tg * 2;
            float b0 = 0.f, b1 = 0.f;
            if (bias) { b0 = bias[col]; b1 = bias[col + 1]; }
            *(float2*)&C[(size_t)r0 * Ncols + col] =
                make_float2(acc[mt][nt][0] + b0, acc[mt][nt][1] + b1);
            *(float2*)&C[(size_t)(r0 + 8) * Ncols + col] =
                make_float2(acc[mt][nt][2] + b0, acc[mt][nt][3] + b1);
        }
    }
    #undef ISSUE_CHUNK
}

// ---------------------------------------------------------------------------
// Fourier attention, MUFU-sin, software-pipelined:
//   cp.async triple-buffered K/V tiles; double-buffered a4 (sS);
//   one sync region holds phase B(t-1) + phase A(t) -> MUFU/FFMA interleave.
// q stored NEGATED so d' = k - q via fadd2 (factor is even in d).
// ---------------------------------------------------------------------------
#define TSZ (KT2 * DH)                  // 2048 floats per K or V tile
static const int ATTN_SMEM = (16 * CH + 6 * TSZ + 2 * KT2 * 33 + 8 * QT) * 4;

__global__ __launch_bounds__(256, 3)
void fourier_attn7(const float* __restrict__ qkv,
                   const float* __restrict__ paramR,
                   __nv_bfloat16* __restrict__ outh,
                   __nv_bfloat16* __restrict__ outl)
{
    extern __shared__ float sm[];
    float* sQn = sm;                        // [16][CH] negated q, chunked
    float* sK  = sQn + 16 * CH;             // 3 x [32][64]
    float* sV  = sK + 3 * TSZ;              // 3 x [32][64]
    float* sS  = sV + 3 * TSZ;              // 2 x [32][33]
    float* sRed = sS + 2 * KT2 * 33;        // [8][32]
    const uint32_t sKb = smem_u32(sK);
    const uint32_t sVb = smem_u32(sV);

    const int tid = threadIdx.x;
    const int q = tid & 31, kg = tid >> 5;
    const int qt = blockIdx.x, h = blockIdx.y, b = blockIdx.z;
    const int tok0 = b * NSEQ, q0 = qt * QT;
    const float R = paramR[0];
    const u64 R2 = pk2(R, R);

    // q-side fill: negated values, chunked [d4][q][4]
    for (int i = tid; i < QT * 16; i += 256) {
        int d4 = i & 15, qq = i >> 4;
        float4 v = *(const float4*)&qkv[(tok0 + q0 + qq) * QKVD + h * DH + d4 * 4];
        *(float4*)&sQn[d4 * CH + qq * 4] = make_float4(-v.x, -v.y, -v.z, -v.w);
    }

    // K/V tile fill via cp.async (2 iters of (K,V) cp16 per thread)
    #define FILL(tt) do {                                                     \
        int bsel_ = (tt) % 3;                                                 \
        _Pragma("unroll")                                                     \
        for (int v_ = 0; v_ < 2; v_++) {                                      \
            int f_ = v_ * 256 + tid;                                          \
            int kk_ = f_ >> 4, dq_ = (f_ & 15) * 4;                           \
            uint32_t so_ = (uint32_t)(bsel_ * TSZ + kk_ * DH + dq_) * 4;      \
            size_t gr_ = (size_t)(tok0 + (tt) * KT2 + kk_) * QKVD + h * DH + dq_; \
            cp16(sKb + so_, &qkv[gr_ + CDIM]);                                \
            cp16(sVb + so_, &qkv[gr_ + 2 * CDIM]);                            \
        }                                                                     \
        asm volatile("cp.async.commit_group;");                               \
    } while (0)

    u64 acc[4];
    #pragma unroll
    for (int i = 0; i < 4; i++) acc[i] = 0ull;
    float rowsum = 0.f;
    const int kb0 = kg * 4 * DH;

    FILL(0);
    FILL(1);

    for (int t = 0; t < NSEQ / KT2; ++t) {
        if (t >= 6) asm volatile("cp.async.wait_group 0;" ::: "memory");
        else        asm volatile("cp.async.wait_group 1;" ::: "memory");
        __syncthreads();

        // ---- phase B(t-1): PV for 8-dim slice over previous tile's keys ----
        if (t > 0) {
            const float* pS = sS + ((t - 1) & 1) * KT2 * 33;
            const float* pV = sV + ((t - 1) % 3) * TSZ;
            #pragma unroll 8
            for (int j = 0; j < KT2; j++) {
                float a = pS[j * 33 + q];
                u64 aa = pk2(a, a);
                const ulonglong2* vp = (const ulonglong2*)&pV[j * DH + kg * 8];
                ulonglong2 v0 = vp[0], v1 = vp[1];
                acc[0] = ffma2(aa, v0.x, acc[0]);
                acc[1] = ffma2(aa, v0.y, acc[1]);
                acc[2] = ffma2(aa, v1.x, acc[2]);
                acc[3] = ffma2(aa, v1.y, acc[3]);
            }
        }

        // ---- phase A(t): scores for this thread's 4 keys ----
        {
            const float* pK = sK + (t % 3) * TSZ;
            float* pS = sS + (t & 1) * KT2 * 33;
            u64 np[4], dp[4];
            #pragma unroll
            for (int j = 0; j < 4; j++) { np[j] = pk2(1.f, 1.f); dp[j] = pk2(1.f, 1.f); }

            #pragma unroll 4
            for (int d4 = 0; d4 < 16; d4++) {
                ulonglong2 qn = *(const ulonglong2*)&sQn[d4 * CH + q * 4];
                #pragma unroll
                for (int j = 0; j < 4; j++) {
                    ulonglong2 kv = *(const ulonglong2*)&pK[kb0 + j * DH + d4 * 4];
                    u64 d01 = fadd2(kv.x, qn.x);           // k - q (= -d, even)
                    u64 d23 = fadd2(kv.y, qn.y);
                    u64 rd01 = fmul2(R2, d01);
                    u64 rd23 = fmul2(R2, d23);
                    float a0, a1, a2, a3;
                    up2(rd01, a0, a1); up2(rd23, a2, a3);
                    float s0 = __sinf(a0), s1 = __sinf(a1);
                    float s2 = __sinf(a2), s3 = __sinf(a3);
                    np[j] = fmul2(np[j], pk2(s0, s1));
                    np[j] = fmul2(np[j], pk2(s2, s3));
                    dp[j] = fmul2(dp[j], d01);
                    dp[j] = fmul2(dp[j], d23);
                }
            }
            #pragma unroll
            for (int j = 0; j < 4; j++) {
                float n0, n1, dd0, dd1;
                up2(np[j], n0, n1); up2(dp[j], dd0, dd1);
                float npp = n0 * n1, dpp = dd0 * dd1;
                float s = (dpp != 0.f) ? npp / dpp : 0.f;
                float s2 = s * s;
                float a4 = s2 * s2;
                rowsum += a4;
                pS[(kg * 4 + j) * 33 + q] = a4;
            }
        }
        __syncthreads();
        if (t + 2 < NSEQ / KT2) FILL(t + 2);
    }

    // ---- phase B(last tile) ----
    {
        const int t = NSEQ / KT2 - 1;
        const float* pS = sS + (t & 1) * KT2 * 33;
        const float* pV = sV + (t % 3) * TSZ;
        #pragma unroll 8
        for (int j = 0; j < KT2; j++) {
            float a = pS[j * 33 + q];
            u64 aa = pk2(a, a);
            const ulonglong2* vp = (const ulonglong2*)&pV[j * DH + kg * 8];
            ulonglong2 v0 = vp[0], v1 = vp[1];
            acc[0] = ffma2(aa, v0.x, acc[0]);
            acc[1] = ffma2(aa, v0.y, acc[1]);
            acc[2] = ffma2(aa, v1.x, acc[2]);
            acc[3] = ffma2(aa, v1.y, acc[3]);
        }
    }
    __syncthreads();

    sRed[kg * 32 + q] = rowsum;
    __syncthreads();
    float ss = 0.f;
    #pragma unroll
    for (int r = 0; r < 8; r++) ss += sRed[r * 32 + q];
    float inv = 1.f / (ss + EPSF);
    u64 inv2 = pk2(inv, inv);

    #pragma unroll
    for (int i = 0; i < 4; i++) acc[i] = fmul2(acc[i], inv2);

    float of[8];
    up2(acc[0], of[0], of[1]); up2(acc[1], of[2], of[3]);
    up2(acc[2], of[4], of[5]); up2(acc[3], of[6], of[7]);

    __nv_bfloat16 hb[8], lb[8];
    #pragma unroll
    for (int i = 0; i < 8; i++) {
        __nv_bfloat16 hh = __float2bfloat16(of[i]);
        hb[i] = hh;
        lb[i] = __float2bfloat16(of[i] - __bfloat162float(hh));
    }
    size_t base = (size_t)(tok0 + q0 + q) * CDIM + h * DH + kg * 8;
    *(uint4*)&outh[base] = *(const uint4*)hb;
    *(uint4*)&outl[base] = *(const uint4*)lb;
    #undef FILL
}

extern "C" void kernel_launch(void* const* d_in, const int* in_sizes, int n_in,
                              void* d_out, int out_size)
{
    const float* x      = (const float*)d_in[0];
    const float* w_qkv  = (const float*)d_in[1];
    const float* w_proj = (const float*)d_in[2];
    const float* b_proj = (const float*)d_in[3];
    const float* paramR = (const float*)d_in[4];
    float* out = (float*)d_out;

    float *qkvbuf;
    __nv_bfloat16 *xh, *xl, *wqh, *wql, *wph, *wpl, *ath, *atl;
    cudaGetSymbolAddress((void**)&qkvbuf, g_qkv);
    cudaGetSymbolAddress((void**)&xh,  g_xh);
    cudaGetSymbolAddress((void**)&xl,  g_xl);
    cudaGetSymbolAddress((void**)&wqh, g_wqh);
    cudaGetSymbolAddress((void**)&wql, g_wql);
    cudaGetSymbolAddress((void**)&wph, g_wph);
    cudaGetSymbolAddress((void**)&wpl, g_wpl);
    cudaGetSymbolAddress((void**)&ath, g_ath);
    cudaGetSymbolAddress((void**)&atl, g_atl);

    cudaFuncSetAttribute(fourier_attn7, cudaFuncAttributeMaxDynamicSharedMemorySize,
                         ATTN_SMEM);
    cudaFuncSetAttribute(hmma_gemm, cudaFuncAttributeMaxDynamicSharedMemorySize,
                         HG_SMEM);

    // 0) merged split of fp32 inputs to bf16 hi/lo
    split_all<<<(NX + NQ + NP) / 256, 256>>>(x, w_qkv, w_proj,
                                             xh, xl, wqh, wql, wph, wpl);

    // 1) qkv = x @ w_qkv^T via HMMA (384 CTAs)
    hmma_gemm<<<dim3(QKVD / 64, TOKENS / 64), 128, HG_SMEM>>>(
        xh, xl, wqh, wql, nullptr, qkvbuf, QKVD);

    // 2) pipelined MUFU-sin attention (256 blocks, 3/SM)
    fourier_attn7<<<dim3(NSEQ / QT, HEADS, 4), 256, ATTN_SMEM>>>(
        qkvbuf, paramR, ath, atl);

    // 3) proj via HMMA (128 CTAs)
    hmma_gemm<<<dim3(CDIM / 64, TOKENS / 64), 128, HG_SMEM>>>(
        ath, atl, wph, wpl, b_proj, out, CDIM);
}